// round 2
// baseline (speedup 1.0000x reference)
#include <cuda_runtime.h>
#include <cstddef>

#define NE 800000
#define NN 50000
#define IN_CH 128
#define HID 64
#define OUT_CH 128

#define RS2 0.70710678118654752f

// Scratch: node hidden state (complex interleaved as [NN][64] floats). 12.8 MB.
__device__ float g_h[(size_t)NN * HID];
__device__ int g_mask_kind;  // 0 = uint8, 1 = int32, 2 = float32

// ---------------------------------------------------------------------------
// Mask dtype detection. undirected_mask is a jax bool array; the harness may
// serialize it as uint8 (1B), int32, or float32. Bernoulli(0.5) data makes the
// byte pattern of the first 16KB unambiguous:
//   uint8 : value-1 bytes appear at indices i%4==1            -> kind 0
//   float : 0x80 at i%4==2 / 0x3F at i%4==3, zero at i%4==1   -> kind 2
//   int32 : nonzero only at i%4==0                            -> kind 1
// Reading 16KB as bytes is safe for every candidate dtype (buffer >= 800KB).
// ---------------------------------------------------------------------------
__global__ void detect_kernel(const unsigned char* __restrict__ m) {
    __shared__ int f1, f23;
    if (threadIdx.x == 0) { f1 = 0; f23 = 0; }
    __syncthreads();
    int lf1 = 0, lf23 = 0;
    for (int i = threadIdx.x; i < 16384; i += blockDim.x) {
        unsigned char b = m[i];
        if (b) {
            int r = i & 3;
            if (r == 1) lf1 = 1;
            else if (r >= 2) lf23 = 1;
        }
    }
    if (lf1) atomicOr(&f1, 1);
    if (lf23) atomicOr(&f23, 1);
    __syncthreads();
    if (threadIdx.x == 0) g_mask_kind = f1 ? 0 : (f23 ? 2 : 1);
}

static __device__ __forceinline__ bool read_mask(const void* m, int kind, int e) {
    if (kind == 0) return ((const unsigned char*)m)[e] != 0;
    if (kind == 1) return ((const int*)m)[e] != 0;
    return ((const float*)m)[e] != 0.0f;
}

// Per-edge constants:
//  undirected: phase=1      -> cc=1,  ss=0,  dinv = (u==v) ? 0 : 2^-1/2
//  directed  : phase=(c,s)  -> cc=c,  ss=s,  dinv = 2^-1/2
static __device__ __forceinline__ void edge_params(
    const int* __restrict__ ei, const void* __restrict__ mraw, int kind, int e,
    int& u, int& v, float& cc, float& ss, float& dinv)
{
    u = ei[e];
    v = ei[NE + e];
    bool und = read_mask(mraw, kind, e);
    if (und) { cc = 1.0f; ss = 0.0f; dinv = (u == v) ? 0.0f : RS2; }
    else     { cc = RS2;  ss = RS2;  dinv = RS2; }
}

// ---------------------------------------------------------------------------
// Stage 1: z = (edge_attr @ W_in^T) * dinv, then scatter
//   h[v] += c_head * z   (c_head = conj(phase) = (cc,-ss))
//   h[u] += c_tail * z   (c_tail = -phase      = (-cc,-ss))
// One warp handles 4 edges; lane l owns complex channel l (outputs 2l, 2l+1).
// W_in^T lives in smem ([128][64], float2 reads conflict-free); edge rows are
// staged in smem and broadcast. Scatter = 4 scalar RED.F32 per lane per edge.
// ---------------------------------------------------------------------------
__global__ void __launch_bounds__(512, 2) scatter_gemm_kernel(
    const float* __restrict__ ea, const float* __restrict__ Win,
    const int* __restrict__ ei, const void* __restrict__ mraw)
{
    extern __shared__ float smC[];
    float* WT = smC;                     // [128][64]: WT[i*64+j] = Win[j*128+i]
    float* aS = smC + IN_CH * HID;       // [16 warps][4 edges][128]
    const int tid = threadIdx.x, wid = tid >> 5, l = tid & 31;
    const int kind = g_mask_kind;

    for (int x = tid; x < IN_CH * HID; x += 512) {
        int i = x >> 6, j = x & 63;
        WT[x] = Win[j * IN_CH + i];
    }
    __syncthreads();

    float* aw = aS + wid * 4 * IN_CH;
    const int gw = blockIdx.x * 16 + wid, nw = gridDim.x * 16;

    for (int g = gw; g < NE / 4; g += nw) {
        const int e0 = g * 4;
        #pragma unroll
        for (int e = 0; e < 4; e++) {
            ((float4*)(aw + e * IN_CH))[l] =
                ((const float4*)(ea + (size_t)(e0 + e) * IN_CH))[l];
        }
        __syncwarp();

        float zr0 = 0.f, zi0 = 0.f, zr1 = 0.f, zi1 = 0.f;
        float zr2 = 0.f, zi2 = 0.f, zr3 = 0.f, zi3 = 0.f;
        #pragma unroll 4
        for (int i = 0; i < IN_CH; i++) {
            float2 w = ((const float2*)WT)[i * 32 + l];  // W_in[2l][i], W_in[2l+1][i]
            float a0 = aw[i], a1 = aw[IN_CH + i];
            float a2 = aw[2 * IN_CH + i], a3 = aw[3 * IN_CH + i];
            zr0 = fmaf(a0, w.x, zr0); zi0 = fmaf(a0, w.y, zi0);
            zr1 = fmaf(a1, w.x, zr1); zi1 = fmaf(a1, w.y, zi1);
            zr2 = fmaf(a2, w.x, zr2); zi2 = fmaf(a2, w.y, zi2);
            zr3 = fmaf(a3, w.x, zr3); zi3 = fmaf(a3, w.y, zi3);
        }
        float zr[4] = {zr0, zr1, zr2, zr3};
        float zi[4] = {zi0, zi1, zi2, zi3};

        #pragma unroll
        for (int e = 0; e < 4; e++) {
            int u, v; float cc, ss, dinv;
            edge_params(ei, mraw, kind, e0 + e, u, v, cc, ss, dinv);
            if (dinv == 0.0f) continue;   // warp-uniform
            float r = zr[e] * dinv, im = zi[e] * dinv;
            // head -> v:  (cc*r + ss*im,  cc*im - ss*r)
            // tail -> u:  (-cc*r + ss*im, -cc*im - ss*r)
            float hr = fmaf(cc, r, ss * im);
            float hi = fmaf(cc, im, -ss * r);
            float tr = fmaf(-cc, r, ss * im);
            float ti = fmaf(-cc, im, -ss * r);
            float* hv = g_h + (size_t)v * HID + 2 * l;
            float* hu = g_h + (size_t)u * HID + 2 * l;
            atomicAdd(hv, hr);
            atomicAdd(hv + 1, hi);
            atomicAdd(hu, tr);
            atomicAdd(hu + 1, ti);
        }
        __syncwarp();
    }
}

// ---------------------------------------------------------------------------
// Stage 2: gather + output GEMMs.
//   y = dinv * ( conj(c_head)*relu(h[v]) + conj(c_tail)*relu(h[u]) )
//   out = real_view(y) @ W_out^T + edge_attr @ W_skip^T + (b_skip + bias)
// ReLU is applied at read time (saves a full pass over h).
// One warp handles 2 edges; lane l owns out channels {l, l+32, l+64, l+96}.
// Weights are stored permuted in smem so each lane's 4 coefficients are one
// LDS.128 (conflict-free).
// ---------------------------------------------------------------------------
__global__ void __launch_bounds__(512, 1) gather_out_kernel(
    const float* __restrict__ ea, const float* __restrict__ Wout,
    const float* __restrict__ Wskip, const float* __restrict__ bskip,
    const float* __restrict__ bias, const int* __restrict__ ei,
    const void* __restrict__ mraw, float* __restrict__ out)
{
    extern __shared__ float sm[];
    float* WoP = sm;             // [64][128]  permuted W_out
    float* WsP = sm + 8192;      // [128][128] permuted W_skip
    float* bv  = sm + 24576;     // [128] b_skip + bias
    float* a2  = sm + 24704;     // [16 warps][2][128] edge rows
    float* y2  = sm + 28800;     // [16 warps][2][64]  y vectors
    const int tid = threadIdx.x, wid = tid >> 5, l = tid & 31;
    const int kind = g_mask_kind;

    // WoP[j*128 + lane*4 + m] = W_out[(lane+32m)*64 + j]
    for (int x = tid; x < 8192; x += 512) {
        int j = x >> 7, t = x & 127;
        int o = (t >> 2) + 32 * (t & 3);
        WoP[x] = Wout[o * HID + j];
    }
    for (int x = tid; x < 16384; x += 512) {
        int i = x >> 7, t = x & 127;
        int o = (t >> 2) + 32 * (t & 3);
        WsP[x] = Wskip[o * IN_CH + i];
    }
    if (tid < 128) bv[tid] = bskip[tid] + bias[tid];
    __syncthreads();

    float* aw = a2 + wid * 2 * IN_CH;
    float* yw = y2 + wid * 2 * HID;
    const int gw = blockIdx.x * 16 + wid, nw = gridDim.x * 16;

    for (int g = gw; g < NE / 2; g += nw) {
        const int e0 = 2 * g;
        #pragma unroll
        for (int e = 0; e < 2; e++)
            ((float4*)(aw + e * IN_CH))[l] =
                ((const float4*)(ea + (size_t)(e0 + e) * IN_CH))[l];

        #pragma unroll
        for (int e = 0; e < 2; e++) {
            int u, v; float cc, ss, dinv;
            edge_params(ei, mraw, kind, e0 + e, u, v, cc, ss, dinv);
            float2 hv = *(const float2*)(g_h + (size_t)v * HID + 2 * l);
            float2 hu = *(const float2*)(g_h + (size_t)u * HID + 2 * l);
            float av = fmaxf(hv.x, 0.f), bvv = fmaxf(hv.y, 0.f);
            float au = fmaxf(hu.x, 0.f), bu  = fmaxf(hu.y, 0.f);
            // conj(c_head)=( cc, ss), conj(c_tail)=(-cc, ss)
            float yr = dinv * (cc * (av - au) - ss * (bvv + bu));
            float yi = dinv * (cc * (bvv - bu) + ss * (av + au));
            yw[e * HID + 2 * l]     = yr;
            yw[e * HID + 2 * l + 1] = yi;
        }
        __syncwarp();

        float a00 = 0.f, a01 = 0.f, a02 = 0.f, a03 = 0.f;
        float a10 = 0.f, a11 = 0.f, a12 = 0.f, a13 = 0.f;
        #pragma unroll 8
        for (int j = 0; j < HID; j++) {
            float4 w = ((const float4*)(WoP + j * 128))[l];
            float y0 = yw[j], y1 = yw[HID + j];
            a00 = fmaf(y0, w.x, a00); a01 = fmaf(y0, w.y, a01);
            a02 = fmaf(y0, w.z, a02); a03 = fmaf(y0, w.w, a03);
            a10 = fmaf(y1, w.x, a10); a11 = fmaf(y1, w.y, a11);
            a12 = fmaf(y1, w.z, a12); a13 = fmaf(y1, w.w, a13);
        }
        #pragma unroll 8
        for (int i = 0; i < IN_CH; i++) {
            float4 w = ((const float4*)(WsP + i * 128))[l];
            float x0 = aw[i], x1 = aw[IN_CH + i];
            a00 = fmaf(x0, w.x, a00); a01 = fmaf(x0, w.y, a01);
            a02 = fmaf(x0, w.z, a02); a03 = fmaf(x0, w.w, a03);
            a10 = fmaf(x1, w.x, a10); a11 = fmaf(x1, w.y, a11);
            a12 = fmaf(x1, w.z, a12); a13 = fmaf(x1, w.w, a13);
        }

        float* o0 = out + (size_t)e0 * OUT_CH;
        o0[l]      = a00 + bv[l];
        o0[l + 32] = a01 + bv[l + 32];
        o0[l + 64] = a02 + bv[l + 64];
        o0[l + 96] = a03 + bv[l + 96];
        float* o1 = o0 + OUT_CH;
        o1[l]      = a10 + bv[l];
        o1[l + 32] = a11 + bv[l + 32];
        o1[l + 64] = a12 + bv[l + 64];
        o1[l + 96] = a13 + bv[l + 96];
        __syncwarp();
    }
}

extern "C" void kernel_launch(void* const* d_in, const int* in_sizes, int n_in,
                              void* d_out, int out_size) {
    (void)in_sizes; (void)n_in; (void)out_size;
    const int*   ei    = (const int*)d_in[0];
    const void*  mask  = d_in[1];
    const float* ea    = (const float*)d_in[2];
    const float* Win   = (const float*)d_in[3];
    const float* Wout  = (const float*)d_in[4];
    const float* Wskip = (const float*)d_in[5];
    const float* bskip = (const float*)d_in[6];
    const float* bias  = (const float*)d_in[7];
    float* out = (float*)d_out;

    int dev = 0;
    cudaGetDevice(&dev);
    int sms = 148;
    cudaDeviceGetAttribute(&sms, cudaDevAttrMultiProcessorCount, dev);

    void* hptr = nullptr;
    cudaGetSymbolAddress(&hptr, g_h);

    cudaFuncSetAttribute(scatter_gemm_kernel,
                         cudaFuncAttributeMaxDynamicSharedMemorySize, 65536);
    cudaFuncSetAttribute(gather_out_kernel,
                         cudaFuncAttributeMaxDynamicSharedMemorySize, 123392);

    detect_kernel<<<1, 256>>>((const unsigned char*)mask);
    cudaMemsetAsync(hptr, 0, sizeof(float) * (size_t)NN * HID);
    scatter_gemm_kernel<<<sms * 2, 512, 65536>>>(ea, Win, ei, mask);
    gather_out_kernel<<<sms, 512, 123392>>>(ea, Wout, Wskip, bskip, bias, ei, mask, out);
}

// round 4
// speedup vs baseline: 1.4392x; 1.4392x over previous
#include <cuda_runtime.h>
#include <cuda_bf16.h>
#include <cstdint>
#include <cstddef>

#define NE 800000
#define NN 50000
#define IN_CH 128
#define HID 64
#define OUT_CH 128
#define NT 6250          // 800000 / 128 edge tiles
#define RS2 0.70710678118654752f

#define P2 200           // smem row pitch in bf16 elements (400 B)
#define A_H 0
#define A_L 51200
#define W_H 102400
#define W_L 153600
#define S_BV 204800
#define SMEM2 205312

// Node hidden state (complex interleaved [NN][64] floats), 12.8 MB scratch.
__device__ float g_h[(size_t)NN * HID];

// ---------------------------------------------------------------------------
// Mask dtype detection (per-block; 2048 bytes of Bernoulli(0.5) data is
// unambiguous across uint8 / int32 / float32 serialization).
// ---------------------------------------------------------------------------
__device__ __forceinline__ int detect_kind(const void* mraw, int* sflags) {
    if (threadIdx.x < 2) sflags[threadIdx.x] = 0;
    __syncthreads();
    int l1 = 0, l23 = 0;
    const unsigned char* m = (const unsigned char*)mraw;
    for (int i = threadIdx.x; i < 2048; i += blockDim.x) {
        unsigned char b = m[i];
        if (b) {
            int r = i & 3;
            if (r == 1) l1 = 1;
            else if (r >= 2) l23 = 1;
        }
    }
    if (l1) atomicOr(&sflags[0], 1);
    if (l23) atomicOr(&sflags[1], 1);
    __syncthreads();
    return sflags[0] ? 0 : (sflags[1] ? 2 : 1);
}
__device__ __forceinline__ bool read_mask(const void* m, int kind, int e) {
    if (kind == 0) return ((const unsigned char*)m)[e] != 0;
    if (kind == 1) return ((const int*)m)[e] != 0;
    return ((const float*)m)[e] != 0.0f;
}

__device__ __forceinline__ void bf16_split(float f, uint16_t& hi, uint16_t& lo) {
    __nv_bfloat16 h = __float2bfloat16(f);
    float r = f - __bfloat162float(h);
    __nv_bfloat16 l = __float2bfloat16(r);
    hi = __bfloat16_as_ushort(h);
    lo = __bfloat16_as_ushort(l);
}

__device__ __forceinline__ void mma16816(float* c, const uint32_t* a,
                                         const uint32_t* b) {
    asm volatile(
        "mma.sync.aligned.m16n8k16.row.col.f32.bf16.bf16.f32 "
        "{%0,%1,%2,%3}, {%4,%5,%6,%7}, {%8,%9}, {%0,%1,%2,%3};"
        : "+f"(c[0]), "+f"(c[1]), "+f"(c[2]), "+f"(c[3])
        : "r"(a[0]), "r"(a[1]), "r"(a[2]), "r"(a[3]), "r"(b[0]), "r"(b[1]));
}

// ---------------------------------------------------------------------------
// Stage 1: z = (edge_attr @ W_in^T) * dinv, rotate, scatter-atomic into g_h.
// ---------------------------------------------------------------------------
__global__ void __launch_bounds__(512, 2) scatter_gemm_kernel(
    const float* __restrict__ ea, const float* __restrict__ Win,
    const int* __restrict__ ei, const void* __restrict__ mraw)
{
    extern __shared__ float smC[];
    __shared__ int sflags[2];
    const int kind = detect_kind(mraw, sflags);

    float* WT = smC;                     // [128][64]: WT[i*64+j] = Win[j*128+i]
    float* aS = smC + IN_CH * HID;       // [16 warps][4 edges][128]
    const int tid = threadIdx.x, wid = tid >> 5, l = tid & 31;

    for (int x = tid; x < IN_CH * HID; x += 512) {
        int i = x >> 6, j = x & 63;
        WT[x] = Win[j * IN_CH + i];
    }
    __syncthreads();

    float* aw = aS + wid * 4 * IN_CH;
    const int gw = blockIdx.x * 16 + wid, nw = gridDim.x * 16;

    for (int g = gw; g < NE / 4; g += nw) {
        const int e0 = g * 4;
        #pragma unroll
        for (int e = 0; e < 4; e++) {
            ((float4*)(aw + e * IN_CH))[l] =
                ((const float4*)(ea + (size_t)(e0 + e) * IN_CH))[l];
        }
        __syncwarp();

        float zr0 = 0.f, zi0 = 0.f, zr1 = 0.f, zi1 = 0.f;
        float zr2 = 0.f, zi2 = 0.f, zr3 = 0.f, zi3 = 0.f;
        #pragma unroll 4
        for (int i = 0; i < IN_CH; i++) {
            float2 w = ((const float2*)WT)[i * 32 + l];
            float a0 = aw[i], a1 = aw[IN_CH + i];
            float a2 = aw[2 * IN_CH + i], a3 = aw[3 * IN_CH + i];
            zr0 = fmaf(a0, w.x, zr0); zi0 = fmaf(a0, w.y, zi0);
            zr1 = fmaf(a1, w.x, zr1); zi1 = fmaf(a1, w.y, zi1);
            zr2 = fmaf(a2, w.x, zr2); zi2 = fmaf(a2, w.y, zi2);
            zr3 = fmaf(a3, w.x, zr3); zi3 = fmaf(a3, w.y, zi3);
        }
        float zr[4] = {zr0, zr1, zr2, zr3};
        float zi[4] = {zi0, zi1, zi2, zi3};

        #pragma unroll
        for (int e = 0; e < 4; e++) {
            int u = ei[e0 + e], v = ei[NE + e0 + e];
            bool und = read_mask(mraw, kind, e0 + e);
            float cc, ss, dinv;
            if (und) { cc = 1.0f; ss = 0.0f; dinv = (u == v) ? 0.0f : RS2; }
            else     { cc = RS2;  ss = RS2;  dinv = RS2; }
            if (dinv == 0.0f) continue;   // warp-uniform
            float r = zr[e] * dinv, im = zi[e] * dinv;
            float hr = fmaf(cc, r, ss * im);
            float hi = fmaf(cc, im, -ss * r);
            float tr = fmaf(-cc, r, ss * im);
            float ti = fmaf(-cc, im, -ss * r);
            float* hv = g_h + (size_t)v * HID + 2 * l;
            float* hu = g_h + (size_t)u * HID + 2 * l;
            atomicAdd(hv, hr);
            atomicAdd(hv + 1, hi);
            atomicAdd(hu, tr);
            atomicAdd(hu + 1, ti);
        }
        __syncwarp();
    }
}

// ---------------------------------------------------------------------------
// Stage 2 (mma.sync bf16): per 128-edge tile
//   Y[r][2l,2l+1] = dinv*( conj(c_head)*relu(h[v]) + conj(c_tail)*relu(h[u]) )
//   A = [Y | EA] (128 x 192), B = [W_out | W_skip] (128 x 192)
//   D = A @ B^T via 3-pass hi/lo bf16 split; out = D + (b_skip + bias)
// A/B stored row-major bf16 with pitch 200 elems (400B) -> conflict-free
// fragment LDS. Warp (wr, wc) computes rows wr*32..+31, cols wc*64..+63.
// ---------------------------------------------------------------------------
__global__ void __launch_bounds__(256, 1) stage2_kernel(
    const float* __restrict__ ea, const float* __restrict__ Wout,
    const float* __restrict__ Wskip, const float* __restrict__ bskip,
    const float* __restrict__ bias, const int* __restrict__ ei,
    const void* __restrict__ mraw, float* __restrict__ out)
{
    extern __shared__ __align__(16) char sm[];
    __shared__ int sflags[2];
    const int tid = threadIdx.x, w = tid >> 5, l = tid & 31;
    const int kind = detect_kind(mraw, sflags);
    float* bv = (float*)(sm + S_BV);

    // ---- Weights -> [W_out | W_skip] hi/lo tiles (done once) ----
    for (int x = tid; x < 128 * 32; x += 256) {         // W_out: k cols 0..63
        int n = x >> 5, kp = x & 31;
        float2 wv = *(const float2*)(Wout + n * HID + 2 * kp);
        uint16_t h0, l0, h1, l1;
        bf16_split(wv.x, h0, l0);
        bf16_split(wv.y, h1, l1);
        uint32_t off = (uint32_t)(n * 400 + 4 * kp);
        *(uint32_t*)(sm + W_H + off) = (uint32_t)h0 | ((uint32_t)h1 << 16);
        *(uint32_t*)(sm + W_L + off) = (uint32_t)l0 | ((uint32_t)l1 << 16);
    }
    for (int x = tid; x < 128 * 64; x += 256) {         // W_skip: k cols 64..191
        int n = x >> 6, kp = x & 63;
        float2 wv = *(const float2*)(Wskip + n * IN_CH + 2 * kp);
        uint16_t h0, l0, h1, l1;
        bf16_split(wv.x, h0, l0);
        bf16_split(wv.y, h1, l1);
        uint32_t off = (uint32_t)(n * 400 + 128 + 4 * kp);
        *(uint32_t*)(sm + W_H + off) = (uint32_t)h0 | ((uint32_t)h1 << 16);
        *(uint32_t*)(sm + W_L + off) = (uint32_t)l0 | ((uint32_t)l1 << 16);
    }
    if (tid < 128) bv[tid] = bskip[tid] + bias[tid];
    __syncthreads();

    const int wr = w >> 1, wc = w & 1;          // 4 x 2 warp grid
    const int g = l >> 2, tig = l & 3;
    const int rowbase = wr * 32, colbase = wc * 64;

    for (int t = blockIdx.x; t < NT; t += gridDim.x) {
        // ---- Phase A: build [Y | EA] hi/lo tile (warp w -> 16 rows) ----
        #pragma unroll 2
        for (int rr = 0; rr < 16; rr++) {
            int r = w * 16 + rr, e = t * 128 + r;
            float4 a4 = *(const float4*)(ea + (size_t)e * IN_CH + 4 * l);
            uint16_t h0, lo0, h1, lo1, h2, lo2, h3, lo3;
            bf16_split(a4.x, h0, lo0); bf16_split(a4.y, h1, lo1);
            bf16_split(a4.z, h2, lo2); bf16_split(a4.w, h3, lo3);
            uint2 hv2, lv2;
            hv2.x = (uint32_t)h0 | ((uint32_t)h1 << 16);
            hv2.y = (uint32_t)h2 | ((uint32_t)h3 << 16);
            lv2.x = (uint32_t)lo0 | ((uint32_t)lo1 << 16);
            lv2.y = (uint32_t)lo2 | ((uint32_t)lo3 << 16);
            uint32_t off = (uint32_t)(r * 400 + 128 + 8 * l);
            *(uint2*)(sm + A_H + off) = hv2;
            *(uint2*)(sm + A_L + off) = lv2;

            int u = ei[e], v = ei[NE + e];
            bool und = read_mask(mraw, kind, e);
            float cc, ss, dinv;
            if (und) { cc = 1.0f; ss = 0.0f; dinv = (u == v) ? 0.0f : RS2; }
            else     { cc = RS2;  ss = RS2;  dinv = RS2; }
            float2 hvv = *(const float2*)(g_h + (size_t)v * HID + 2 * l);
            float2 huu = *(const float2*)(g_h + (size_t)u * HID + 2 * l);
            float av = fmaxf(hvv.x, 0.f), bvv = fmaxf(hvv.y, 0.f);
            float au = fmaxf(huu.x, 0.f), bu  = fmaxf(huu.y, 0.f);
            float yr = dinv * (cc * (av - au) - ss * (bvv + bu));
            float yi = dinv * (cc * (bvv - bu) + ss * (av + au));
            uint16_t yh0, yl0, yh1, yl1;
            bf16_split(yr, yh0, yl0);
            bf16_split(yi, yh1, yl1);
            uint32_t off2 = (uint32_t)(r * 400 + 4 * l);
            *(uint32_t*)(sm + A_H + off2) = (uint32_t)yh0 | ((uint32_t)yh1 << 16);
            *(uint32_t*)(sm + A_L + off2) = (uint32_t)yl0 | ((uint32_t)yl1 << 16);
        }
        __syncthreads();

        // ---- Phase B: 3-pass hi/lo mma.sync over K=192 ----
        float acc[2][8][4];
        #pragma unroll
        for (int mf = 0; mf < 2; mf++)
            #pragma unroll
            for (int nf = 0; nf < 8; nf++)
                #pragma unroll
                for (int i = 0; i < 4; i++) acc[mf][nf][i] = 0.f;

        #pragma unroll 1
        for (int pass = 0; pass < 3; pass++) {
            const char* Ab = sm + (pass == 1 ? A_L : A_H);
            const char* Bb = sm + (pass == 2 ? W_L : W_H);
            #pragma unroll 2
            for (int ks = 0; ks < 12; ks++) {
                const int kb = ks * 32 + 4 * tig;   // byte offset of k-chunk
                uint32_t a[2][4];
                #pragma unroll
                for (int mf = 0; mf < 2; mf++) {
                    const char* ap = Ab + (rowbase + mf * 16 + g) * 400 + kb;
                    a[mf][0] = *(const uint32_t*)(ap);
                    a[mf][1] = *(const uint32_t*)(ap + 8 * 400);
                    a[mf][2] = *(const uint32_t*)(ap + 16);
                    a[mf][3] = *(const uint32_t*)(ap + 8 * 400 + 16);
                }
                #pragma unroll
                for (int nf = 0; nf < 8; nf++) {
                    const char* bp = Bb + (colbase + nf * 8 + g) * 400 + kb;
                    uint32_t b[2];
                    b[0] = *(const uint32_t*)(bp);
                    b[1] = *(const uint32_t*)(bp + 16);
                    mma16816(acc[0][nf], a[0], b);
                    mma16816(acc[1][nf], a[1], b);
                }
            }
        }

        // ---- Phase C: bias + coalesced stores from register fragments ----
        #pragma unroll
        for (int mf = 0; mf < 2; mf++) {
            int e0 = t * 128 + rowbase + mf * 16 + g;
            #pragma unroll
            for (int nf = 0; nf < 8; nf++) {
                int c = colbase + nf * 8 + 2 * tig;
                float2 bb = *(const float2*)(bv + c);
                float2 v0, v1;
                v0.x = acc[mf][nf][0] + bb.x;
                v0.y = acc[mf][nf][1] + bb.y;
                v1.x = acc[mf][nf][2] + bb.x;
                v1.y = acc[mf][nf][3] + bb.y;
                *(float2*)(out + (size_t)e0 * OUT_CH + c) = v0;
                *(float2*)(out + (size_t)(e0 + 8) * OUT_CH + c) = v1;
            }
        }
        __syncthreads();
    }
}

extern "C" void kernel_launch(void* const* d_in, const int* in_sizes, int n_in,
                              void* d_out, int out_size) {
    (void)in_sizes; (void)n_in; (void)out_size;
    const int*   ei    = (const int*)d_in[0];
    const void*  mask  = d_in[1];
    const float* ea    = (const float*)d_in[2];
    const float* Win   = (const float*)d_in[3];
    const float* Wout  = (const float*)d_in[4];
    const float* Wskip = (const float*)d_in[5];
    const float* bskip = (const float*)d_in[6];
    const float* bias  = (const float*)d_in[7];
    float* out = (float*)d_out;

    int dev = 0;
    cudaGetDevice(&dev);
    int sms = 148;
    cudaDeviceGetAttribute(&sms, cudaDevAttrMultiProcessorCount, dev);

    void* hptr = nullptr;
    cudaGetSymbolAddress(&hptr, g_h);

    cudaFuncSetAttribute(scatter_gemm_kernel,
                         cudaFuncAttributeMaxDynamicSharedMemorySize, 65536);
    cudaFuncSetAttribute(stage2_kernel,
                         cudaFuncAttributeMaxDynamicSharedMemorySize, SMEM2);

    cudaMemsetAsync(hptr, 0, sizeof(float) * (size_t)NN * HID);
    scatter_gemm_kernel<<<sms * 2, 512, 65536>>>(ea, Win, ei, mask);
    stage2_kernel<<<sms, 256, SMEM2>>>(ea, Wout, Wskip, bskip, bias, ei, mask, out);
}

// round 5
// speedup vs baseline: 2.0388x; 1.4166x over previous
#include <cuda_runtime.h>
#include <cuda_bf16.h>
#include <cstdint>
#include <cstddef>

#define NE 800000
#define NN 50000
#define IN_CH 128
#define HID 64
#define OUT_CH 128
#define NT 6250          // 800000 / 128 edge tiles
#define RS2 0.70710678118654752f

// ---- stage2 smem (bytes), A/B rows pitch 400B (200 bf16) ----
#define A_H 0
#define A_L 51200
#define W_H 102400
#define W_L 153600
#define S_BV 204800
#define SMEM2 205312

// ---- stage1 smem (bytes), pitch 272B (136 bf16) ----
#define S1_A_H 0
#define S1_A_L 34816
#define S1_W_H 69632
#define S1_W_L 87040
#define SMEM1  104448

// Node hidden state (complex interleaved [NN][64] floats), 12.8 MB scratch.
__device__ float g_h[(size_t)NN * HID];

// ---------------------------------------------------------------------------
// Helpers
// ---------------------------------------------------------------------------
__device__ __forceinline__ uint32_t smem_u32(const void* p) {
    uint32_t a;
    asm("{ .reg .u64 t; cvta.to.shared.u64 t, %1; cvt.u32.u64 %0, t; }"
        : "=r"(a) : "l"(p));
    return a;
}

__device__ __forceinline__ int detect_kind(const void* mraw, int* sflags) {
    if (threadIdx.x < 2) sflags[threadIdx.x] = 0;
    __syncthreads();
    int l1 = 0, l23 = 0;
    const unsigned char* m = (const unsigned char*)mraw;
    for (int i = threadIdx.x; i < 2048; i += blockDim.x) {
        unsigned char b = m[i];
        if (b) {
            int r = i & 3;
            if (r == 1) l1 = 1;
            else if (r >= 2) l23 = 1;
        }
    }
    if (l1) atomicOr(&sflags[0], 1);
    if (l23) atomicOr(&sflags[1], 1);
    __syncthreads();
    return sflags[0] ? 0 : (sflags[1] ? 2 : 1);
}
__device__ __forceinline__ bool read_mask(const void* m, int kind, int e) {
    if (kind == 0) return ((const unsigned char*)m)[e] != 0;
    if (kind == 1) return ((const int*)m)[e] != 0;
    return ((const float*)m)[e] != 0.0f;
}

__device__ __forceinline__ void bf16_split(float f, uint16_t& hi, uint16_t& lo) {
    __nv_bfloat16 h = __float2bfloat16(f);
    float r = f - __bfloat162float(h);
    __nv_bfloat16 l = __float2bfloat16(r);
    hi = __bfloat16_as_ushort(h);
    lo = __bfloat16_as_ushort(l);
}

__device__ __forceinline__ void mma16816(float* c, const uint32_t* a,
                                         const uint32_t* b) {
    asm volatile(
        "mma.sync.aligned.m16n8k16.row.col.f32.bf16.bf16.f32 "
        "{%0,%1,%2,%3}, {%4,%5,%6,%7}, {%8,%9}, {%0,%1,%2,%3};"
        : "+f"(c[0]), "+f"(c[1]), "+f"(c[2]), "+f"(c[3])
        : "r"(a[0]), "r"(a[1]), "r"(a[2]), "r"(a[3]), "r"(b[0]), "r"(b[1]));
}

#define LDSM4(r, addr)                                                         \
    asm volatile("ldmatrix.sync.aligned.m8n8.x4.shared.b16 {%0,%1,%2,%3}, [%4];"\
        : "=r"((r)[0]), "=r"((r)[1]), "=r"((r)[2]), "=r"((r)[3]) : "r"(addr))

__device__ __forceinline__ void red_v4(float* p, float a, float b, float c,
                                       float d) {
    asm volatile("red.global.add.v4.f32 [%0], {%1,%2,%3,%4};"
                 :: "l"(p), "f"(a), "f"(b), "f"(c), "f"(d) : "memory");
}

// ---------------------------------------------------------------------------
// Stage 1 (mma.sync): z = (EA @ W_in^T)  [128x64 per tile, 3-pass hi/lo],
// then rotate + red.v4 scatter into g_h.
// Warp grid 4x4: warp tile 32 rows x 16 cols.
// ---------------------------------------------------------------------------
__global__ void __launch_bounds__(512, 2) stage1_kernel(
    const float* __restrict__ ea, const float* __restrict__ Win,
    const int* __restrict__ ei, const void* __restrict__ mraw)
{
    extern __shared__ __align__(16) char sm1[];
    __shared__ int sflags[2];
    const int tid = threadIdx.x, w = tid >> 5, l = tid & 31;
    const int kind = detect_kind(mraw, sflags);
    const uint32_t sb = smem_u32(sm1);

    // W_in [64][128] -> hi/lo bf16, pitch 272B
    for (int x = tid; x < 64 * 64; x += 512) {
        int n = x >> 6, kp = x & 63;
        float2 wv = *(const float2*)(Win + n * IN_CH + 2 * kp);
        uint16_t h0, l0, h1, l1;
        bf16_split(wv.x, h0, l0);
        bf16_split(wv.y, h1, l1);
        uint32_t off = (uint32_t)(n * 272 + 4 * kp);
        *(uint32_t*)(sm1 + S1_W_H + off) = (uint32_t)h0 | ((uint32_t)h1 << 16);
        *(uint32_t*)(sm1 + S1_W_L + off) = (uint32_t)l0 | ((uint32_t)l1 << 16);
    }

    const int wr = w >> 2, wc = w & 3;
    const int rowb = wr * 32, colb = wc * 16;
    const int g = l >> 2, tig = l & 3;
    // ldmatrix per-thread address templates (byte offsets into a tile)
    const uint32_t a_sub = (uint32_t)((rowb + ((l >> 3) & 1) * 8 + (l & 7)) * 272
                                      + (l >> 4) * 16);
    const uint32_t b_sub = (uint32_t)((colb + ((l >> 4) & 1) * 8 + (l & 7)) * 272
                                      + ((l >> 3) & 1) * 16);
    float* zt = (float*)(sm1 + S1_A_H);   // reused as z tile [128][68] fp32

    for (int t = blockIdx.x; t < NT; t += gridDim.x) {
        // ---- build EA hi/lo tile: warp w -> rows w*8 .. w*8+7 ----
        __syncthreads();   // protect A_H (z of previous tile) until scatter done
        #pragma unroll 2
        for (int rr = 0; rr < 8; rr++) {
            int r = w * 8 + rr, e = t * 128 + r;
            float4 a4 = *(const float4*)(ea + (size_t)e * IN_CH + 4 * l);
            uint16_t h0, lo0, h1, lo1, h2, lo2, h3, lo3;
            bf16_split(a4.x, h0, lo0); bf16_split(a4.y, h1, lo1);
            bf16_split(a4.z, h2, lo2); bf16_split(a4.w, h3, lo3);
            uint2 hv2, lv2;
            hv2.x = (uint32_t)h0 | ((uint32_t)h1 << 16);
            hv2.y = (uint32_t)h2 | ((uint32_t)h3 << 16);
            lv2.x = (uint32_t)lo0 | ((uint32_t)lo1 << 16);
            lv2.y = (uint32_t)lo2 | ((uint32_t)lo3 << 16);
            uint32_t off = (uint32_t)(r * 272 + 8 * l);
            *(uint2*)(sm1 + S1_A_H + off) = hv2;
            *(uint2*)(sm1 + S1_A_L + off) = lv2;
        }
        __syncthreads();

        // ---- 3-pass hi/lo mma over K=128 ----
        float acc[2][2][4];
        #pragma unroll
        for (int mf = 0; mf < 2; mf++)
            #pragma unroll
            for (int nf = 0; nf < 2; nf++)
                #pragma unroll
                for (int i = 0; i < 4; i++) acc[mf][nf][i] = 0.f;

        #pragma unroll 1
        for (int pass = 0; pass < 3; pass++) {
            uint32_t Ab = sb + (pass == 1 ? S1_A_L : S1_A_H);
            uint32_t Bb = sb + (pass == 2 ? S1_W_L : S1_W_H);
            uint32_t aa0 = Ab + a_sub, aa1 = aa0 + 16 * 272;
            uint32_t ba = Bb + b_sub;
            #pragma unroll
            for (int ks = 0; ks < 8; ks++) {
                uint32_t A0[4], A1[4], B0[4];
                LDSM4(A0, aa0);
                LDSM4(A1, aa1);
                LDSM4(B0, ba);
                mma16816(acc[0][0], A0, B0);
                mma16816(acc[0][1], A0, B0 + 2);
                mma16816(acc[1][0], A1, B0);
                mma16816(acc[1][1], A1, B0 + 2);
                aa0 += 32; aa1 += 32; ba += 32;
            }
        }
        __syncthreads();   // all warps done reading A tiles -> reuse as z

        // ---- write z fragments to smem [128][68] ----
        #pragma unroll
        for (int mf = 0; mf < 2; mf++) {
            int row = rowb + mf * 16 + g;
            #pragma unroll
            for (int nf = 0; nf < 2; nf++) {
                int n = colb + nf * 8 + 2 * tig;
                *(float2*)(zt + row * 68 + n) =
                    make_float2(acc[mf][nf][0], acc[mf][nf][1]);
                *(float2*)(zt + (row + 8) * 68 + n) =
                    make_float2(acc[mf][nf][2], acc[mf][nf][3]);
            }
        }
        __syncthreads();

        // ---- scatter: 4 threads per edge, red.v4 per 16B ----
        {
            int el = tid >> 2, q = tid & 3;
            int e = t * 128 + el;
            int u = ei[e], v = ei[NE + e];
            bool und = read_mask(mraw, kind, e);
            float cc, ss, dinv;
            if (und) { cc = 1.0f; ss = 0.0f; dinv = (u == v) ? 0.0f : RS2; }
            else     { cc = RS2;  ss = RS2;  dinv = RS2; }
            if (dinv != 0.0f) {
                const float* zr = zt + el * 68 + 16 * q;
                float* hv = g_h + (size_t)v * HID + 16 * q;
                float* hu = g_h + (size_t)u * HID + 16 * q;
                #pragma unroll
                for (int j = 0; j < 4; j++) {
                    float4 z4 = *(const float4*)(zr + 4 * j);
                    float r0 = z4.x * dinv, i0 = z4.y * dinv;
                    float r1 = z4.z * dinv, i1 = z4.w * dinv;
                    red_v4(hv + 4 * j,
                           fmaf(cc, r0, ss * i0), fmaf(cc, i0, -ss * r0),
                           fmaf(cc, r1, ss * i1), fmaf(cc, i1, -ss * r1));
                    red_v4(hu + 4 * j,
                           fmaf(-cc, r0, ss * i0), fmaf(-cc, i0, -ss * r0),
                           fmaf(-cc, r1, ss * i1), fmaf(-cc, i1, -ss * r1));
                }
            }
        }
    }
}

// ---------------------------------------------------------------------------
// Stage 2 (mma.sync, 16 warps, ldmatrix): per 128-edge tile
//   A = [Y | EA] (128 x 192), B = [W_out | W_skip] (128 x 192)
//   D = A @ B^T (3-pass hi/lo); out = D + (b_skip + bias)
// Warp grid 4x4: warp tile 32 rows x 32 cols.
// ---------------------------------------------------------------------------
__global__ void __launch_bounds__(512, 1) stage2_kernel(
    const float* __restrict__ ea, const float* __restrict__ Wout,
    const float* __restrict__ Wskip, const float* __restrict__ bskip,
    const float* __restrict__ bias, const int* __restrict__ ei,
    const void* __restrict__ mraw, float* __restrict__ out)
{
    extern __shared__ __align__(16) char sm[];
    __shared__ int sflags[2];
    const int tid = threadIdx.x, w = tid >> 5, l = tid & 31;
    const int kind = detect_kind(mraw, sflags);
    const uint32_t sb = smem_u32(sm);
    float* bv = (float*)(sm + S_BV);

    for (int x = tid; x < 128 * 32; x += 512) {         // W_out: k 0..63
        int n = x >> 5, kp = x & 31;
        float2 wv = *(const float2*)(Wout + n * HID + 2 * kp);
        uint16_t h0, l0, h1, l1;
        bf16_split(wv.x, h0, l0);
        bf16_split(wv.y, h1, l1);
        uint32_t off = (uint32_t)(n * 400 + 4 * kp);
        *(uint32_t*)(sm + W_H + off) = (uint32_t)h0 | ((uint32_t)h1 << 16);
        *(uint32_t*)(sm + W_L + off) = (uint32_t)l0 | ((uint32_t)l1 << 16);
    }
    for (int x = tid; x < 128 * 64; x += 512) {         // W_skip: k 64..191
        int n = x >> 6, kp = x & 63;
        float2 wv = *(const float2*)(Wskip + n * IN_CH + 2 * kp);
        uint16_t h0, l0, h1, l1;
        bf16_split(wv.x, h0, l0);
        bf16_split(wv.y, h1, l1);
        uint32_t off = (uint32_t)(n * 400 + 128 + 4 * kp);
        *(uint32_t*)(sm + W_H + off) = (uint32_t)h0 | ((uint32_t)h1 << 16);
        *(uint32_t*)(sm + W_L + off) = (uint32_t)l0 | ((uint32_t)l1 << 16);
    }
    if (tid < 128) bv[tid] = bskip[tid] + bias[tid];
    __syncthreads();

    const int wr = w >> 2, wc = w & 3;
    const int rowb = wr * 32, colb = wc * 32;
    const int g = l >> 2, tig = l & 3;
    const uint32_t a_sub = (uint32_t)((rowb + ((l >> 3) & 1) * 8 + (l & 7)) * 400
                                      + (l >> 4) * 16);
    const uint32_t b_sub = (uint32_t)((colb + ((l >> 4) & 1) * 8 + (l & 7)) * 400
                                      + ((l >> 3) & 1) * 16);

    for (int t = blockIdx.x; t < NT; t += gridDim.x) {
        // ---- Phase A: build [Y | EA] hi/lo tile (warp w -> 8 rows) ----
        #pragma unroll 2
        for (int rr = 0; rr < 8; rr++) {
            int r = w * 8 + rr, e = t * 128 + r;
            float4 a4 = *(const float4*)(ea + (size_t)e * IN_CH + 4 * l);
            uint16_t h0, lo0, h1, lo1, h2, lo2, h3, lo3;
            bf16_split(a4.x, h0, lo0); bf16_split(a4.y, h1, lo1);
            bf16_split(a4.z, h2, lo2); bf16_split(a4.w, h3, lo3);
            uint2 hv2, lv2;
            hv2.x = (uint32_t)h0 | ((uint32_t)h1 << 16);
            hv2.y = (uint32_t)h2 | ((uint32_t)h3 << 16);
            lv2.x = (uint32_t)lo0 | ((uint32_t)lo1 << 16);
            lv2.y = (uint32_t)lo2 | ((uint32_t)lo3 << 16);
            uint32_t off = (uint32_t)(r * 400 + 128 + 8 * l);
            *(uint2*)(sm + A_H + off) = hv2;
            *(uint2*)(sm + A_L + off) = lv2;

            int u = ei[e], v = ei[NE + e];
            bool und = read_mask(mraw, kind, e);
            float cc, ss, dinv;
            if (und) { cc = 1.0f; ss = 0.0f; dinv = (u == v) ? 0.0f : RS2; }
            else     { cc = RS2;  ss = RS2;  dinv = RS2; }
            float2 hvv = *(const float2*)(g_h + (size_t)v * HID + 2 * l);
            float2 huu = *(const float2*)(g_h + (size_t)u * HID + 2 * l);
            float av = fmaxf(hvv.x, 0.f), bvv = fmaxf(hvv.y, 0.f);
            float au = fmaxf(huu.x, 0.f), bu  = fmaxf(huu.y, 0.f);
            float yr = dinv * (cc * (av - au) - ss * (bvv + bu));
            float yi = dinv * (cc * (bvv - bu) + ss * (av + au));
            uint16_t yh0, yl0, yh1, yl1;
            bf16_split(yr, yh0, yl0);
            bf16_split(yi, yh1, yl1);
            uint32_t off2 = (uint32_t)(r * 400 + 4 * l);
            *(uint32_t*)(sm + A_H + off2) = (uint32_t)yh0 | ((uint32_t)yh1 << 16);
            *(uint32_t*)(sm + A_L + off2) = (uint32_t)yl0 | ((uint32_t)yl1 << 16);
        }
        __syncthreads();

        // ---- Phase B: 3-pass hi/lo mma over K=192 ----
        float acc[2][4][4];
        #pragma unroll
        for (int mf = 0; mf < 2; mf++)
            #pragma unroll
            for (int nf = 0; nf < 4; nf++)
                #pragma unroll
                for (int i = 0; i < 4; i++) acc[mf][nf][i] = 0.f;

        #pragma unroll 1
        for (int pass = 0; pass < 3; pass++) {
            uint32_t Ab = sb + (pass == 1 ? A_L : A_H);
            uint32_t Bb = sb + (pass == 2 ? W_L : W_H);
            uint32_t aa0 = Ab + a_sub, aa1 = aa0 + 16 * 400;
            uint32_t ba0 = Bb + b_sub, ba1 = ba0 + 16 * 400;
            #pragma unroll 4
            for (int ks = 0; ks < 12; ks++) {
                uint32_t A0[4], A1[4], B0[4], B1[4];
                LDSM4(A0, aa0);
                LDSM4(A1, aa1);
                LDSM4(B0, ba0);
                LDSM4(B1, ba1);
                mma16816(acc[0][0], A0, B0);
                mma16816(acc[0][1], A0, B0 + 2);
                mma16816(acc[0][2], A0, B1);
                mma16816(acc[0][3], A0, B1 + 2);
                mma16816(acc[1][0], A1, B0);
                mma16816(acc[1][1], A1, B0 + 2);
                mma16816(acc[1][2], A1, B1);
                mma16816(acc[1][3], A1, B1 + 2);
                aa0 += 32; aa1 += 32; ba0 += 32; ba1 += 32;
            }
        }

        // ---- Phase C: bias + coalesced stores ----
        #pragma unroll
        for (int mf = 0; mf < 2; mf++) {
            int e0 = t * 128 + rowb + mf * 16 + g;
            #pragma unroll
            for (int nf = 0; nf < 4; nf++) {
                int c = colb + nf * 8 + 2 * tig;
                float2 bb = *(const float2*)(bv + c);
                float2 v0, v1;
                v0.x = acc[mf][nf][0] + bb.x;
                v0.y = acc[mf][nf][1] + bb.y;
                v1.x = acc[mf][nf][2] + bb.x;
                v1.y = acc[mf][nf][3] + bb.y;
                *(float2*)(out + (size_t)e0 * OUT_CH + c) = v0;
                *(float2*)(out + (size_t)(e0 + 8) * OUT_CH + c) = v1;
            }
        }
        __syncthreads();
    }
}

extern "C" void kernel_launch(void* const* d_in, const int* in_sizes, int n_in,
                              void* d_out, int out_size) {
    (void)in_sizes; (void)n_in; (void)out_size;
    const int*   ei    = (const int*)d_in[0];
    const void*  mask  = d_in[1];
    const float* ea    = (const float*)d_in[2];
    const float* Win   = (const float*)d_in[3];
    const float* Wout  = (const float*)d_in[4];
    const float* Wskip = (const float*)d_in[5];
    const float* bskip = (const float*)d_in[6];
    const float* bias  = (const float*)d_in[7];
    float* out = (float*)d_out;

    int dev = 0;
    cudaGetDevice(&dev);
    int sms = 148;
    cudaDeviceGetAttribute(&sms, cudaDevAttrMultiProcessorCount, dev);

    void* hptr = nullptr;
    cudaGetSymbolAddress(&hptr, g_h);

    cudaFuncSetAttribute(stage1_kernel,
                         cudaFuncAttributeMaxDynamicSharedMemorySize, SMEM1);
    cudaFuncSetAttribute(stage2_kernel,
                         cudaFuncAttributeMaxDynamicSharedMemorySize, SMEM2);

    cudaMemsetAsync(hptr, 0, sizeof(float) * (size_t)NN * HID);
    stage1_kernel<<<sms * 2, 512, SMEM1>>>(ea, Win, ei, mask);
    stage2_kernel<<<sms, 512, SMEM2>>>(ea, Wout, Wskip, bskip, bias, ei, mask, out);
}

// round 7
// speedup vs baseline: 2.5352x; 1.2435x over previous
#include <cuda_runtime.h>
#include <cuda_bf16.h>
#include <cstdint>
#include <cstddef>

#define NE 800000
#define NN 50000
#define IN_CH 128
#define HID 64
#define OUT_CH 128
#define NT 6250          // 800000 / 128 edge tiles
#define RS2 0.70710678118654752f

// ---- stage2 smem (bytes), A/B rows pitch 400B (200 bf16) ----
#define A_H 0
#define A_L 51200
#define W_H 102400
#define W_L 153600
#define S_BV 204800
#define SMEM2 205312

// ---- stage1 smem (bytes), pitch 272B (136 bf16) ----
#define S1_A_H 0
#define S1_A_L 34816
#define S1_W_H 69632
#define S1_W_L 87040
#define SMEM1  104448

// Node hidden state (complex interleaved [NN][64] floats), 12.8 MB scratch.
__device__ float g_h[(size_t)NN * HID];

// ---------------------------------------------------------------------------
// Helpers
// ---------------------------------------------------------------------------
__device__ __forceinline__ uint32_t smem_u32(const void* p) {
    uint32_t a;
    asm("{ .reg .u64 t; cvta.to.shared.u64 t, %1; cvt.u32.u64 %0, t; }"
        : "=r"(a) : "l"(p));
    return a;
}

__device__ __forceinline__ int detect_kind(const void* mraw, int* sflags) {
    if (threadIdx.x < 2) sflags[threadIdx.x] = 0;
    __syncthreads();
    int l1 = 0, l23 = 0;
    const unsigned char* m = (const unsigned char*)mraw;
    for (int i = threadIdx.x; i < 2048; i += blockDim.x) {
        unsigned char b = m[i];
        if (b) {
            int r = i & 3;
            if (r == 1) l1 = 1;
            else if (r >= 2) l23 = 1;
        }
    }
    if (l1) atomicOr(&sflags[0], 1);
    if (l23) atomicOr(&sflags[1], 1);
    __syncthreads();
    return sflags[0] ? 0 : (sflags[1] ? 2 : 1);
}
__device__ __forceinline__ bool read_mask(const void* m, int kind, int e) {
    if (kind == 0) return ((const unsigned char*)m)[e] != 0;
    if (kind == 1) return ((const int*)m)[e] != 0;
    return ((const float*)m)[e] != 0.0f;
}

__device__ __forceinline__ void bf16_split(float f, uint16_t& hi, uint16_t& lo) {
    __nv_bfloat16 h = __float2bfloat16(f);
    float r = f - __bfloat162float(h);
    __nv_bfloat16 l = __float2bfloat16(r);
    hi = __bfloat16_as_ushort(h);
    lo = __bfloat16_as_ushort(l);
}

__device__ __forceinline__ void mma16816(float* c, const uint32_t* a,
                                         const uint32_t* b) {
    asm volatile(
        "mma.sync.aligned.m16n8k16.row.col.f32.bf16.bf16.f32 "
        "{%0,%1,%2,%3}, {%4,%5,%6,%7}, {%8,%9}, {%0,%1,%2,%3};"
        : "+f"(c[0]), "+f"(c[1]), "+f"(c[2]), "+f"(c[3])
        : "r"(a[0]), "r"(a[1]), "r"(a[2]), "r"(a[3]), "r"(b[0]), "r"(b[1]));
}

#define LDSM4(r, addr)                                                         \
    asm volatile("ldmatrix.sync.aligned.m8n8.x4.shared.b16 {%0,%1,%2,%3}, [%4];"\
        : "=r"((r)[0]), "=r"((r)[1]), "=r"((r)[2]), "=r"((r)[3]) : "r"(addr))

__device__ __forceinline__ void red_v4(float* p, float a, float b, float c,
                                       float d) {
    asm volatile("red.global.add.v4.f32 [%0], {%1,%2,%3,%4};"
                 :: "l"(p), "f"(a), "f"(b), "f"(c), "f"(d) : "memory");
}

// lane-split metadata: lanes 0-7 load u(row), 8-15 v(row), 16-23 mask(row)
__device__ __forceinline__ int load_lane_meta(const int* __restrict__ ei,
                                              const void* __restrict__ m,
                                              int kind, int eb, int l) {
    if (l < 8) return ei[eb + l];
    if (l < 16) return ei[NE + eb + (l - 8)];
    if (l < 24) {
        int e = eb + (l - 16);
        if (kind == 0) return ((const unsigned char*)m)[e];
        if (kind == 1) return ((const int*)m)[e];
        return (((const float*)m)[e] != 0.0f) ? 1 : 0;
    }
    return 0;
}

__device__ __forceinline__ void issue_gathers(int pre, int l, float2* phv,
                                              float2* phu) {
    #pragma unroll
    for (int r = 0; r < 8; r++) {
        int u = __shfl_sync(0xffffffffu, pre, r);
        int v = __shfl_sync(0xffffffffu, pre, r + 8);
        phv[r] = *(const float2*)(g_h + (size_t)v * HID + 2 * l);
        phu[r] = *(const float2*)(g_h + (size_t)u * HID + 2 * l);
    }
}

// ---------------------------------------------------------------------------
// Stage 1 (mma.sync): z = (EA @ W_in^T), rotate + red.v4 scatter into g_h.
// ---------------------------------------------------------------------------
__global__ void __launch_bounds__(512, 2) stage1_kernel(
    const float* __restrict__ ea, const float* __restrict__ Win,
    const int* __restrict__ ei, const void* __restrict__ mraw)
{
    extern __shared__ __align__(16) char sm1[];
    __shared__ int sflags[2];
    const int tid = threadIdx.x, w = tid >> 5, l = tid & 31;
    const int kind = detect_kind(mraw, sflags);
    const uint32_t sb = smem_u32(sm1);

    for (int x = tid; x < 64 * 64; x += 512) {
        int n = x >> 6, kp = x & 63;
        float2 wv = *(const float2*)(Win + n * IN_CH + 2 * kp);
        uint16_t h0, l0, h1, l1;
        bf16_split(wv.x, h0, l0);
        bf16_split(wv.y, h1, l1);
        uint32_t off = (uint32_t)(n * 272 + 4 * kp);
        *(uint32_t*)(sm1 + S1_W_H + off) = (uint32_t)h0 | ((uint32_t)h1 << 16);
        *(uint32_t*)(sm1 + S1_W_L + off) = (uint32_t)l0 | ((uint32_t)l1 << 16);
    }

    const int wr = w >> 2, wc = w & 3;
    const int rowb = wr * 32, colb = wc * 16;
    const int g = l >> 2, tig = l & 3;
    const uint32_t a_sub = (uint32_t)((rowb + ((l >> 3) & 1) * 8 + (l & 7)) * 272
                                      + (l >> 4) * 16);
    const uint32_t b_sub = (uint32_t)((colb + ((l >> 4) & 1) * 8 + (l & 7)) * 272
                                      + ((l >> 3) & 1) * 16);
    float* zt = (float*)(sm1 + S1_A_H);   // reused as z tile [128][68] fp32

    for (int t = blockIdx.x; t < NT; t += gridDim.x) {
        __syncthreads();   // protect A_H (z of previous tile) until scatter done
        #pragma unroll 2
        for (int rr = 0; rr < 8; rr++) {
            int r = w * 8 + rr, e = t * 128 + r;
            float4 a4 = *(const float4*)(ea + (size_t)e * IN_CH + 4 * l);
            uint16_t h0, lo0, h1, lo1, h2, lo2, h3, lo3;
            bf16_split(a4.x, h0, lo0); bf16_split(a4.y, h1, lo1);
            bf16_split(a4.z, h2, lo2); bf16_split(a4.w, h3, lo3);
            uint2 hv2, lv2;
            hv2.x = (uint32_t)h0 | ((uint32_t)h1 << 16);
            hv2.y = (uint32_t)h2 | ((uint32_t)h3 << 16);
            lv2.x = (uint32_t)lo0 | ((uint32_t)lo1 << 16);
            lv2.y = (uint32_t)lo2 | ((uint32_t)lo3 << 16);
            uint32_t off = (uint32_t)(r * 272 + 8 * l);
            *(uint2*)(sm1 + S1_A_H + off) = hv2;
            *(uint2*)(sm1 + S1_A_L + off) = lv2;
        }
        __syncthreads();

        float acc[2][2][4];
        #pragma unroll
        for (int mf = 0; mf < 2; mf++)
            #pragma unroll
            for (int nf = 0; nf < 2; nf++)
                #pragma unroll
                for (int i = 0; i < 4; i++) acc[mf][nf][i] = 0.f;

        #pragma unroll 1
        for (int pass = 0; pass < 3; pass++) {
            uint32_t Ab = sb + (pass == 1 ? S1_A_L : S1_A_H);
            uint32_t Bb = sb + (pass == 2 ? S1_W_L : S1_W_H);
            uint32_t aa0 = Ab + a_sub, aa1 = aa0 + 16 * 272;
            uint32_t ba = Bb + b_sub;
            #pragma unroll
            for (int ks = 0; ks < 8; ks++) {
                uint32_t A0[4], A1[4], B0[4];
                LDSM4(A0, aa0);
                LDSM4(A1, aa1);
                LDSM4(B0, ba);
                mma16816(acc[0][0], A0, B0);
                mma16816(acc[0][1], A0, B0 + 2);
                mma16816(acc[1][0], A1, B0);
                mma16816(acc[1][1], A1, B0 + 2);
                aa0 += 32; aa1 += 32; ba += 32;
            }
        }
        __syncthreads();   // all warps done reading A tiles -> reuse as z

        #pragma unroll
        for (int mf = 0; mf < 2; mf++) {
            int row = rowb + mf * 16 + g;
            #pragma unroll
            for (int nf = 0; nf < 2; nf++) {
                int n = colb + nf * 8 + 2 * tig;
                *(float2*)(zt + row * 68 + n) =
                    make_float2(acc[mf][nf][0], acc[mf][nf][1]);
                *(float2*)(zt + (row + 8) * 68 + n) =
                    make_float2(acc[mf][nf][2], acc[mf][nf][3]);
            }
        }
        __syncthreads();

        {
            int el = tid >> 2, q = tid & 3;
            int e = t * 128 + el;
            int u = ei[e], v = ei[NE + e];
            bool und = read_mask(mraw, kind, e);
            float cc, ss, dinv;
            if (und) { cc = 1.0f; ss = 0.0f; dinv = (u == v) ? 0.0f : RS2; }
            else     { cc = RS2;  ss = RS2;  dinv = RS2; }
            if (dinv != 0.0f) {
                const float* zr = zt + el * 68 + 16 * q;
                float* hv = g_h + (size_t)v * HID + 16 * q;
                float* hu = g_h + (size_t)u * HID + 16 * q;
                #pragma unroll
                for (int j = 0; j < 4; j++) {
                    float4 z4 = *(const float4*)(zr + 4 * j);
                    float r0 = z4.x * dinv, i0 = z4.y * dinv;
                    float r1 = z4.z * dinv, i1 = z4.w * dinv;
                    red_v4(hv + 4 * j,
                           fmaf(cc, r0, ss * i0), fmaf(cc, i0, -ss * r0),
                           fmaf(cc, r1, ss * i1), fmaf(cc, i1, -ss * r1));
                    red_v4(hu + 4 * j,
                           fmaf(-cc, r0, ss * i0), fmaf(-cc, i0, -ss * r0),
                           fmaf(-cc, r1, ss * i1), fmaf(-cc, i1, -ss * r1));
                }
            }
        }
    }
}

// ---------------------------------------------------------------------------
// Stage 2 (mma.sync, 16 warps, ldmatrix, pipelined gathers): per 128-edge tile
//   A = [Y | EA] (128 x 192), B = [W_out | W_skip] (128 x 192)
//   D = A @ B^T (3-pass hi/lo); out = D + (b_skip + bias)
// Next tile's ei/mask load at end of Phase A; its g_h gathers issue between
// MMA pass 0 and pass 1 so ~2/3 of the HMMA work hides their latency.
// ---------------------------------------------------------------------------
__device__ __forceinline__ void s2_pass(uint32_t Ab, uint32_t Bb,
                                        uint32_t a_sub, uint32_t b_sub,
                                        float (&acc)[2][4][4]) {
    uint32_t aa0 = Ab + a_sub, aa1 = aa0 + 16 * 400;
    uint32_t ba0 = Bb + b_sub, ba1 = ba0 + 16 * 400;
    #pragma unroll 4
    for (int ks = 0; ks < 12; ks++) {
        uint32_t A0[4], A1[4], B0[4], B1[4];
        LDSM4(A0, aa0);
        LDSM4(A1, aa1);
        LDSM4(B0, ba0);
        LDSM4(B1, ba1);
        mma16816(acc[0][0], A0, B0);
        mma16816(acc[0][1], A0, B0 + 2);
        mma16816(acc[0][2], A0, B1);
        mma16816(acc[0][3], A0, B1 + 2);
        mma16816(acc[1][0], A1, B0);
        mma16816(acc[1][1], A1, B0 + 2);
        mma16816(acc[1][2], A1, B1);
        mma16816(acc[1][3], A1, B1 + 2);
        aa0 += 32; aa1 += 32; ba0 += 32; ba1 += 32;
    }
}

__global__ void __launch_bounds__(512, 1) stage2_kernel(
    const float* __restrict__ ea, const float* __restrict__ Wout,
    const float* __restrict__ Wskip, const float* __restrict__ bskip,
    const float* __restrict__ bias, const int* __restrict__ ei,
    const void* __restrict__ mraw, float* __restrict__ out)
{
    extern __shared__ __align__(16) char sm[];
    __shared__ int sflags[2];
    const int tid = threadIdx.x, w = tid >> 5, l = tid & 31;
    const int kind = detect_kind(mraw, sflags);
    const uint32_t sb = smem_u32(sm);
    float* bv = (float*)(sm + S_BV);

    for (int x = tid; x < 128 * 32; x += 512) {         // W_out: k 0..63
        int n = x >> 5, kp = x & 31;
        float2 wv = *(const float2*)(Wout + n * HID + 2 * kp);
        uint16_t h0, l0, h1, l1;
        bf16_split(wv.x, h0, l0);
        bf16_split(wv.y, h1, l1);
        uint32_t off = (uint32_t)(n * 400 + 4 * kp);
        *(uint32_t*)(sm + W_H + off) = (uint32_t)h0 | ((uint32_t)h1 << 16);
        *(uint32_t*)(sm + W_L + off) = (uint32_t)l0 | ((uint32_t)l1 << 16);
    }
    for (int x = tid; x < 128 * 64; x += 512) {         // W_skip: k 64..191
        int n = x >> 6, kp = x & 63;
        float2 wv = *(const float2*)(Wskip + n * IN_CH + 2 * kp);
        uint16_t h0, l0, h1, l1;
        bf16_split(wv.x, h0, l0);
        bf16_split(wv.y, h1, l1);
        uint32_t off = (uint32_t)(n * 400 + 128 + 4 * kp);
        *(uint32_t*)(sm + W_H + off) = (uint32_t)h0 | ((uint32_t)h1 << 16);
        *(uint32_t*)(sm + W_L + off) = (uint32_t)l0 | ((uint32_t)l1 << 16);
    }
    if (tid < 128) bv[tid] = bskip[tid] + bias[tid];
    __syncthreads();

    const int wr = w >> 2, wc = w & 3;
    const int rowb = wr * 32, colb = wc * 32;
    const int g = l >> 2, tig = l & 3;
    const uint32_t a_sub = (uint32_t)((rowb + ((l >> 3) & 1) * 8 + (l & 7)) * 400
                                      + (l >> 4) * 16);
    const uint32_t b_sub = (uint32_t)((colb + ((l >> 4) & 1) * 8 + (l & 7)) * 400
                                      + ((l >> 3) & 1) * 16);

    // Prologue: indices + gathers for first tile (one-time exposed latency)
    const int t0 = blockIdx.x;
    int pre = 0;
    float2 phv[8], phu[8];
    if (t0 < NT) {
        pre = load_lane_meta(ei, mraw, kind, t0 * 128 + w * 8, l);
        issue_gathers(pre, l, phv, phu);
    }

    for (int t = t0; t < NT; t += gridDim.x) {
        // ---- Phase A: consume prefetched gathers, stream EA (MLP-4) ----
        #pragma unroll
        for (int b = 0; b < 2; b++) {
            float4 a4[4];
            #pragma unroll
            for (int rr = 0; rr < 4; rr++) {
                int e = t * 128 + w * 8 + b * 4 + rr;
                a4[rr] = *(const float4*)(ea + (size_t)e * IN_CH + 4 * l);
            }
            #pragma unroll
            for (int rr = 0; rr < 4; rr++) {
                int r = w * 8 + b * 4 + rr;
                uint16_t h0, lo0, h1, lo1, h2, lo2, h3, lo3;
                bf16_split(a4[rr].x, h0, lo0); bf16_split(a4[rr].y, h1, lo1);
                bf16_split(a4[rr].z, h2, lo2); bf16_split(a4[rr].w, h3, lo3);
                uint2 hv2, lv2;
                hv2.x = (uint32_t)h0 | ((uint32_t)h1 << 16);
                hv2.y = (uint32_t)h2 | ((uint32_t)h3 << 16);
                lv2.x = (uint32_t)lo0 | ((uint32_t)lo1 << 16);
                lv2.y = (uint32_t)lo2 | ((uint32_t)lo3 << 16);
                uint32_t off = (uint32_t)(r * 400 + 128 + 8 * l);
                *(uint2*)(sm + A_H + off) = hv2;
                *(uint2*)(sm + A_L + off) = lv2;

                int rq = b * 4 + rr;
                int u = __shfl_sync(0xffffffffu, pre, rq);
                int v = __shfl_sync(0xffffffffu, pre, rq + 8);
                int mm = __shfl_sync(0xffffffffu, pre, rq + 16);
                float cc, ss, dinv;
                if (mm) { cc = 1.0f; ss = 0.0f; dinv = (u == v) ? 0.0f : RS2; }
                else    { cc = RS2;  ss = RS2;  dinv = RS2; }
                float av = fmaxf(phv[rq].x, 0.f), bvv = fmaxf(phv[rq].y, 0.f);
                float au = fmaxf(phu[rq].x, 0.f), bu  = fmaxf(phu[rq].y, 0.f);
                float yr = dinv * (cc * (av - au) - ss * (bvv + bu));
                float yi = dinv * (cc * (bvv - bu) + ss * (av + au));
                uint16_t yh0, yl0, yh1, yl1;
                bf16_split(yr, yh0, yl0);
                bf16_split(yi, yh1, yl1);
                uint32_t off2 = (uint32_t)(r * 400 + 4 * l);
                *(uint32_t*)(sm + A_H + off2) = (uint32_t)yh0 | ((uint32_t)yh1 << 16);
                *(uint32_t*)(sm + A_L + off2) = (uint32_t)yl0 | ((uint32_t)yl1 << 16);
            }
        }
        // prefetch next tile's indices (land during pass 0)
        const int tn = t + gridDim.x;
        int pre_n = 0;
        if (tn < NT)
            pre_n = load_lane_meta(ei, mraw, kind, tn * 128 + w * 8, l);
        __syncthreads();

        // ---- Phase B: 3-pass hi/lo; gathers for next tile issue after p0 ----
        float acc[2][4][4];
        #pragma unroll
        for (int mf = 0; mf < 2; mf++)
            #pragma unroll
            for (int nf = 0; nf < 4; nf++)
                #pragma unroll
                for (int i = 0; i < 4; i++) acc[mf][nf][i] = 0.f;

        s2_pass(sb + A_H, sb + W_H, a_sub, b_sub, acc);
        pre = pre_n;
        if (tn < NT) issue_gathers(pre, l, phv, phu);
        s2_pass(sb + A_L, sb + W_H, a_sub, b_sub, acc);
        s2_pass(sb + A_H, sb + W_L, a_sub, b_sub, acc);

        // ---- Phase C: bias + coalesced stores ----
        #pragma unroll
        for (int mf = 0; mf < 2; mf++) {
            int e0 = t * 128 + rowb + mf * 16 + g;
            #pragma unroll
            for (int nf = 0; nf < 4; nf++) {
                int c = colb + nf * 8 + 2 * tig;
                float2 bb = *(const float2*)(bv + c);
                float2 v0, v1;
                v0.x = acc[mf][nf][0] + bb.x;
                v0.y = acc[mf][nf][1] + bb.y;
                v1.x = acc[mf][nf][2] + bb.x;
                v1.y = acc[mf][nf][3] + bb.y;
                *(float2*)(out + (size_t)e0 * OUT_CH + c) = v0;
                *(float2*)(out + (size_t)(e0 + 8) * OUT_CH + c) = v1;
            }
        }
        __syncthreads();
    }
}

extern "C" void kernel_launch(void* const* d_in, const int* in_sizes, int n_in,
                              void* d_out, int out_size) {
    (void)in_sizes; (void)n_in; (void)out_size;
    const int*   ei    = (const int*)d_in[0];
    const void*  mask  = d_in[1];
    const float* ea    = (const float*)d_in[2];
    const float* Win   = (const float*)d_in[3];
    const float* Wout  = (const float*)d_in[4];
    const float* Wskip = (const float*)d_in[5];
    const float* bskip = (const float*)d_in[6];
    const float* bias  = (const float*)d_in[7];
    float* out = (float*)d_out;

    int dev = 0;
    cudaGetDevice(&dev);
    int sms = 148;
    cudaDeviceGetAttribute(&sms, cudaDevAttrMultiProcessorCount, dev);

    void* hptr = nullptr;
    cudaGetSymbolAddress(&hptr, g_h);

    cudaFuncSetAttribute(stage1_kernel,
                         cudaFuncAttributeMaxDynamicSharedMemorySize, SMEM1);
    cudaFuncSetAttribute(stage2_kernel,
                         cudaFuncAttributeMaxDynamicSharedMemorySize, SMEM2);

    cudaMemsetAsync(hptr, 0, sizeof(float) * (size_t)NN * HID);
    stage1_kernel<<<sms * 2, 512, SMEM1>>>(ea, Win, ei, mask);
    stage2_kernel<<<sms, 512, SMEM2>>>(ea, Wout, Wskip, bskip, bias, ei, mask, out);
}